// round 13
// baseline (speedup 1.0000x reference)
#include <cuda_runtime.h>
#include <cuda_bf16.h>

// Shapes (fixed): char_feats [L=512, B=256, D=256] f32 (time-major),
// word_ids/attention_mask [B, L] i32, out = [W=128,B,D] f32 ++ [W,B] f32
#define Lc 512
#define Bc 256
#define Dc 256
#define Wc 128
#define GW 8          // words per block
#define DEPTH 16      // cp.async smem ring depth (rows in flight)

// ---------------------------------------------------------------------------
// Single fused kernel. grid = (Wc/GW=16, Bc), block = 64 threads (one float4
// lane over D each).
//   A) cache word_ids row in smem (int4), sum attn row
//   B) binary-search the 9 group boundaries (ids sorted+densified)
//   C) masks
//   D) stream the group's contiguous char run through a 16-deep cp.async
//      smem ring: each thread copies & consumes ITS OWN 16 B per row, so
//      ordering is per-thread (wait_group), no block syncs in the loop.
// Group accounting (audited): prime commits DEPTH groups (group k = row l+k).
// At loop iter i, committed = DEPTH+i groups; wait_group DEPTH-1 leaves the
// 15 newest pending => first i+1 groups complete => row l+i is readable.
// ---------------------------------------------------------------------------
__global__ __launch_bounds__(64) void fused_kernel(
    const float4* __restrict__ cf,      // [L, B, D/4]
    const int*    __restrict__ word_ids,// [B, L]
    const int*    __restrict__ attn,    // [B, L]
    float4* __restrict__ out,           // [W, B, D/4]
    float*  __restrict__ mask_out)      // [W, B]
{
    const int lane = threadIdx.x;       // 0..63
    const int b    = blockIdx.y;
    const int w0   = blockIdx.x * GW;

    __shared__ int    s_ids[Lc];
    __shared__ int    sE[GW + 1];
    __shared__ int    s_red[2];
    __shared__ float4 s_buf[DEPTH][64];

    // ---- A: cache word_ids row (int4), sum attn row ----
    {
        const int4* wrow = (const int4*)(word_ids + b * Lc);   // 128 int4
        const int4* arow = (const int4*)(attn + b * Lc);
        int4* sd = (int4*)s_ids;
        int asum = 0;
        #pragma unroll
        for (int k = 0; k < 2; ++k) {
            const int idx = lane + k * 64;
            sd[idx] = wrow[idx];
            const int4 a = arow[idx];
            asum += a.x + a.y + a.z + a.w;
        }
        #pragma unroll
        for (int o = 16; o > 0; o >>= 1) asum += __shfl_down_sync(0xffffffffu, asum, o);
        if ((lane & 31) == 0) s_red[lane >> 5] = asum;
    }
    __syncthreads();

    const int cap = (s_red[0] + s_red[1] - 2) + 1;   // valid l in [1, cap)
    const int wn  = s_ids[Lc - 1] + 1;

    // ---- B: binary search boundaries (lanes 0..GW) + clamp ----
    if (lane <= GW) {
        const int target = w0 + lane;
        int lo = 0, hi = Lc;
        while (lo < hi) {
            const int mid = (lo + hi) >> 1;
            if (s_ids[mid] < target) lo = mid + 1; else hi = mid;
        }
        int s = lo;
        s = (s < 1) ? 1 : s;
        s = (s > cap) ? cap : s;
        sE[lane] = s;
    }

    // ---- C: masks ----
    if (lane < GW) mask_out[(w0 + lane) * Bc + b] = (w0 + lane < wn) ? 1.0f : 0.0f;
    __syncthreads();

    // ---- D: stream through cp.async smem ring ----
    const size_t stride = (size_t)Bc * (Dc / 4);
    const float4* cfb = cf + ((size_t)b * (Dc / 4) + lane);
    float4* ob = out + (((size_t)w0 * Bc + b) * (Dc / 4) + lane);
    const size_t wstep = (size_t)Bc * (Dc / 4);

    const float4 zero = make_float4(0.f, 0.f, 0.f, 0.f);

    int l    = sE[0];
    const int lend = sE[GW];
    int wi   = 0;
    int e_cur  = l;
    int e_next = sE[1];
    float4 acc = zero;

    // leading empty words (and fully-empty group)
    while (wi < GW && e_next == l) {
        ob[(size_t)wi * wstep] = zero;
        e_cur = e_next;
        ++wi;
        e_next = (wi < GW) ? sE[wi + 1] : 0x7fffffff;
    }

    const int n = lend - l;
    if (n <= 0) return;

    // per-thread smem slot addresses (thread reads back what it writes)
    const unsigned sb =
        (unsigned)__cvta_generic_to_shared(&s_buf[0][0]) + lane * 16u;

#define CP16(slot, row)                                                     \
    asm volatile("cp.async.cg.shared.global [%0], [%1], 16;"                \
                 :: "r"(sb + (unsigned)((slot) << 10)),                     \
                    "l"(cfb + (size_t)(row) * stride) : "memory")
#define CPCOMMIT() asm volatile("cp.async.commit_group;" ::: "memory")
#define CPWAIT()   asm volatile("cp.async.wait_group %0;" :: "n"(DEPTH - 1) : "memory")

    // prime: one commit group per slot (empty groups keep the count aligned)
    #pragma unroll
    for (int k = 0; k < DEPTH; ++k) {
        if (k < n) CP16(k, l + k);
        CPCOMMIT();
    }

    int i = 0;
    while (i < n) {
        CPWAIT();                                   // row i copy complete
        const float4 v = s_buf[i & (DEPTH - 1)][lane];
        acc.x += v.x; acc.y += v.y; acc.z += v.z; acc.w += v.w;

        const int pf = i + DEPTH;                   // refill same slot
        if (pf < n) CP16(i & (DEPTH - 1), l + pf);
        CPCOMMIT();

        const int gl = l + i + 1;                   // rows consumed so far end
        ++i;

        while (wi < GW && gl == e_next) {
            const int cnt = e_next - e_cur;
            const float inv = 1.0f / (float)(cnt > 0 ? cnt : 1);
            float4 r;
            r.x = acc.x * inv; r.y = acc.y * inv;
            r.z = acc.z * inv; r.w = acc.w * inv;
            ob[(size_t)wi * wstep] = r;
            acc = zero;
            e_cur = e_next;
            ++wi;
            e_next = (wi < GW) ? sE[wi + 1] : 0x7fffffff;
        }
    }
#undef CP16
#undef CPCOMMIT
#undef CPWAIT
}

// ---------------------------------------------------------------------------
extern "C" void kernel_launch(void* const* d_in, const int* in_sizes, int n_in,
                              void* d_out, int out_size) {
    const float* char_feats = (const float*)d_in[0];
    const int*   word_ids   = (const int*)d_in[1];
    const int*   attn       = (const int*)d_in[2];

    float* out_feats = (float*)d_out;
    float* out_mask  = out_feats + (size_t)Wc * Bc * Dc;

    fused_kernel<<<dim3(Wc / GW, Bc), 64>>>(
        (const float4*)char_feats, word_ids, attn,
        (float4*)out_feats, out_mask);
}

// round 14
// speedup vs baseline: 1.1145x; 1.1145x over previous
#include <cuda_runtime.h>
#include <cuda_bf16.h>

// Shapes (fixed): char_feats [L=512, B=256, D=256] f32 (time-major),
// word_ids/attention_mask [B, L] i32, out = [W=128,B,D] f32 ++ [W,B] f32
#define Lc 512
#define Bc 256
#define Dc 256
#define Wc 128
#define CH 64                 // l-rows per chunk (fixed work per block)
#define NCH (Lc / CH)         // 8 chunks
#define NB 2                  // batch rows per block
#define THREADS (NB * 64)

// ---------------------------------------------------------------------------
// Chunk-ownership fused kernel. grid = (NCH, Bc/NB), block = 128 threads =
// 2 subs x 64 float4-lanes. Each sub (one batch row):
//   A) caches its sorted word_ids row in smem, sums attn row
//   B) chunk c owns every word whose clipped run START lies in
//      [c*CH, min((c+1)*CH, cap)); streams from the first owned start to the
//      end of the last owned word (binary search), 4-deep register ring
//   C) empty/invalid words (clipped start == cap) zero-stored by the chunk
//      containing cap; masks striped w = c (mod NCH)
// No atomics, no global scratch, one launch, fixed ~64-row work per block.
// ---------------------------------------------------------------------------
__global__ __launch_bounds__(THREADS, 9) void fused_kernel(
    const float4* __restrict__ cf,      // [L, B, D/4]
    const int*    __restrict__ word_ids,// [B, L]
    const int*    __restrict__ attn,    // [B, L]
    float4* __restrict__ out,           // [W, B, D/4]
    float*  __restrict__ mask_out)      // [W, B]
{
    const int t    = threadIdx.x;
    const int sub  = t >> 6;
    const int lane = t & 63;            // float4 lane over D
    const int c    = blockIdx.x;        // l-chunk
    const int b    = blockIdx.y * NB + sub;

    __shared__ int s_ids[NB][Lc];
    __shared__ int s_red[NB][2];

    // ---- A: cache word_ids row (int4), sum attn row ----
    {
        const int4* wrow = (const int4*)(word_ids + b * Lc);   // 128 int4
        const int4* arow = (const int4*)(attn + b * Lc);
        int4* sd = (int4*)s_ids[sub];
        int asum = 0;
        #pragma unroll
        for (int k = 0; k < 2; ++k) {
            const int idx = lane + k * 64;
            sd[idx] = wrow[idx];
            const int4 a = arow[idx];
            asum += a.x + a.y + a.z + a.w;
        }
        #pragma unroll
        for (int o = 16; o > 0; o >>= 1) asum += __shfl_down_sync(0xffffffffu, asum, o);
        if ((lane & 31) == 0) s_red[sub][lane >> 5] = asum;
    }
    __syncthreads();

    const int* ids = s_ids[sub];
    int cap = s_red[sub][0] + s_red[sub][1] - 1;   // (sum-2)+1: valid l in [1,cap)
    if (cap < 1) cap = 1;
    if (cap > Lc - 1) cap = Lc - 1;                // sum <= 512 => cap <= 511
    const int wn = ids[Lc - 1] + 1;

    // ---- C1: masks, striped (16 words per chunk per row) ----
    if (lane < Wc / NCH) {
        const int w2 = c + lane * NCH;
        mask_out[w2 * Bc + b] = (w2 < wn) ? 1.0f : 0.0f;
    }

    const float4 zero = make_float4(0.f, 0.f, 0.f, 0.f);

    // ---- C2: zero duty — chunk containing cap owns all words whose clipped
    //          start == cap (tail-clipped words and w >= wn) ----
    if ((cap >> 6) == c) {
        const int w_lo = (cap >= 2) ? ids[cap - 1] + 1 : 0;
        for (int w2 = w_lo; w2 < Wc; ++w2)
            out[((size_t)w2 * Bc + b) * (Dc / 4) + lane] = zero;
    }

    // ---- B: find owned range [l0, E) ----
    const int win_lo = c * CH;
    const int win_hi = min(win_lo + CH, cap);
    int l0 = max(win_lo, 1);
    if (l0 >= win_hi) return;
    if (c > 0) {
        // skip continuation of previous chunk's word (its start isn't ours)
        while (l0 < win_hi && ids[l0] == ids[l0 - 1]) ++l0;
    }
    if (l0 >= win_hi) return;

    const int wlast = ids[win_hi - 1];              // last owned word
    int lo = win_hi, hi = Lc;                       // find end of wlast's run
    while (lo < hi) {
        const int mid = (lo + hi) >> 1;
        if (ids[mid] <= wlast) lo = mid + 1; else hi = mid;
    }
    const int E = min(lo, cap);
    const int n = E - l0;                           // rows to stream (>=1)

    const size_t stride = (size_t)Bc * (Dc / 4);
    const float4* p = cf + ((size_t)l0 * Bc + b) * (Dc / 4) + lane;

    // prime 4-deep register ring
    float4 p0 = zero, p1 = zero, p2 = zero, p3 = zero;
    if (0 < n) p0 = p[0 * stride];
    if (1 < n) p1 = p[1 * stride];
    if (2 < n) p2 = p[2 * stride];
    if (3 < n) p3 = p[3 * stride];
    int lpf = 4;

    float4 acc = zero;
    int i = 0;
    int w      = ids[l0];
    int wstart = l0;

#define STEP(P)                                                              \
    {                                                                        \
        const float4 v = P;                                                  \
        if (lpf < n) P = p[(size_t)lpf * stride];                            \
        ++lpf;                                                               \
        acc.x += v.x; acc.y += v.y; acc.z += v.z; acc.w += v.w;              \
        const int gl = l0 + i;                                               \
        ++i;                                                                 \
        if (gl + 1 == E || ids[gl + 1] != w) {                               \
            const int cnt = (gl + 1) - wstart;                               \
            const float inv = 1.0f / (float)cnt;                             \
            float4 r;                                                        \
            r.x = acc.x * inv; r.y = acc.y * inv;                            \
            r.z = acc.z * inv; r.w = acc.w * inv;                            \
            out[((size_t)w * Bc + b) * (Dc / 4) + lane] = r;                 \
            acc = zero;                                                      \
            if (gl + 1 < E) { w = ids[gl + 1]; wstart = gl + 1; }            \
        }                                                                    \
    }

    while (i < n) {
        STEP(p0); if (i >= n) break;
        STEP(p1); if (i >= n) break;
        STEP(p2); if (i >= n) break;
        STEP(p3);
    }
#undef STEP
}

// ---------------------------------------------------------------------------
extern "C" void kernel_launch(void* const* d_in, const int* in_sizes, int n_in,
                              void* d_out, int out_size) {
    const float* char_feats = (const float*)d_in[0];
    const int*   word_ids   = (const int*)d_in[1];
    const int*   attn       = (const int*)d_in[2];

    float* out_feats = (float*)d_out;
    float* out_mask  = out_feats + (size_t)Wc * Bc * Dc;

    fused_kernel<<<dim3(NCH, Bc / NB), THREADS>>>(
        (const float4*)char_feats, word_ids, attn,
        (float4*)out_feats, out_mask);
}